// round 8
// baseline (speedup 1.0000x reference)
#include <cuda_runtime.h>
#include <cuda_fp16.h>
#include <cstdint>

#define NN 8192
#define D 64
#define DO 128
#define K 16

typedef unsigned long long u64;
typedef unsigned int u32;
typedef unsigned short u16;

// Scratch (no dynamic allocs allowed)
__device__ float g_sq[NN];
__device__ float g_p[NN * DO];
__device__ float g_q[NN * DO];
__device__ u16 g_xh[NN * D];            // fp16 copy of x
__device__ u16 g_dist[(size_t)NN * NN]; // sign-transformed fp16 distances (128MB)
__device__ int g_nbr[NN * K];

// sign-transform 2 packed fp16 -> monotone u16 keys (ascending = smaller dist)
__device__ __forceinline__ u32 xform2(u32 u) {
    u32 s = (u >> 15) & 0x00010001u;
    u32 xm = 0x80008000u | (s * 0x7FFFu);
    return u ^ xm;
}

// ---------------------------------------------------------------------------
// Kernel 1: sq norms, p = x@(W1a-W1b)+b1, q = x@W1b, fp16 copy of x.
// ---------------------------------------------------------------------------
__global__ __launch_bounds__(256) void pq_kernel(const float* __restrict__ x,
                                                 const float* __restrict__ W1,
                                                 const float* __restrict__ b1) {
    __shared__ float sx[8 * D];
    const int i0 = blockIdx.x * 8;
    const int t = threadIdx.x;

    for (int u = t; u < 8 * D; u += 256) sx[u] = x[i0 * D + u];
    __syncthreads();

    for (int u = t; u < 8 * D; u += 256) {
        __half h = __float2half_rn(sx[u]);
        g_xh[(size_t)i0 * D + u] = __half_as_ushort(h);
    }

    if (t < 8) {
        float s = 0.f;
        #pragma unroll
        for (int d = 0; d < D; d++) { float v = sx[t * D + d]; s = fmaf(v, v, s); }
        g_sq[i0 + t] = s;
    }

    float acc[8];
    #pragma unroll
    for (int m = 0; m < 8; m++) acc[m] = 0.f;

    if (t < DO) {
        const int c = t;
        for (int d = 0; d < D; d++) {
            float w = W1[d * DO + c] - W1[(D + d) * DO + c];
            #pragma unroll
            for (int m = 0; m < 8; m++) acc[m] = fmaf(sx[m * D + d], w, acc[m]);
        }
        float bb = b1[c];
        #pragma unroll
        for (int m = 0; m < 8; m++) g_p[(size_t)(i0 + m) * DO + c] = acc[m] + bb;
    } else {
        const int c = t - DO;
        for (int d = 0; d < D; d++) {
            float w = W1[(D + d) * DO + c];
            #pragma unroll
            for (int m = 0; m < 8; m++) acc[m] = fmaf(sx[m * D + d], w, acc[m]);
        }
        #pragma unroll
        for (int m = 0; m < 8; m++) g_q[(size_t)(i0 + m) * DO + c] = acc[m];
    }
}

// ---------------------------------------------------------------------------
// Kernel 2: distance matrix via fp16 mma.sync m16n8k16, fp32 accumulate.
// grid (64,64); block 256 thr / 8 warps; tile 128i x 128j; K=64 = 4 k-steps.
// Warp w: rows (w&3)*32, cols (w>>2)*64. Output: transformed fp16 u16.
// smem: A[128][72] f16, B[128][72] f16, sq; dist tile overlays A/B after sync.
// ---------------------------------------------------------------------------
#define PK 72                 // u16 pitch for A/B tiles (conflict-free LDS.32)
#define PDT 136               // u16 pitch for dist tile
#define SM_B_OFF (128 * PK)                 // in u16 units: 9216
#define SM_SQ_OFF (2 * 128 * PK * 2)        // byte offset 36864
#define DIST_SMEM (36864 + 1024)

__global__ __launch_bounds__(256) void dist_kernel() {
    extern __shared__ char smraw[];
    u16* smA = reinterpret_cast<u16*>(smraw);
    u16* smB = smA + SM_B_OFF;
    float* sqi = reinterpret_cast<float*>(smraw + SM_SQ_OFF);
    float* sqj = sqi + 128;
    u16* dt = smA;   // overlay after MMA

    const int t = threadIdx.x;
    const int lane = t & 31, w = t >> 5;
    const int gid = lane >> 2, ctid = lane & 3;
    const int wi = (w & 3) * 32, wj = (w >> 2) * 64;
    const int ib = blockIdx.x * 128, jb = blockIdx.y * 128;

    // Stage tiles: 128 rows x 64 f16 = 128B/row -> 8 uint4 per row.
    for (int u = t; u < 128 * 8; u += 256) {
        int r = u >> 3, q = u & 7;
        uint4 va = reinterpret_cast<const uint4*>(g_xh + (size_t)(ib + r) * D)[q];
        *reinterpret_cast<uint4*>(smA + r * PK + q * 8) = va;
        uint4 vb = reinterpret_cast<const uint4*>(g_xh + (size_t)(jb + r) * D)[q];
        *reinterpret_cast<uint4*>(smB + r * PK + q * 8) = vb;
    }
    if (t < 128) { sqi[t] = g_sq[ib + t]; sqj[t] = g_sq[jb + t]; }
    __syncthreads();

    float acc[2][8][4];
    #pragma unroll
    for (int mt = 0; mt < 2; mt++)
        #pragma unroll
        for (int nt = 0; nt < 8; nt++)
            #pragma unroll
            for (int e = 0; e < 4; e++) acc[mt][nt][e] = 0.f;

    #pragma unroll
    for (int ks = 0; ks < 4; ks++) {
        const int k0 = ks * 16;
        u32 af[2][4], bf[8][2];
        #pragma unroll
        for (int mt = 0; mt < 2; mt++) {
            const u16* pa = smA + (wi + mt * 16 + gid) * PK + k0 + ctid * 2;
            af[mt][0] = *reinterpret_cast<const u32*>(pa);
            af[mt][1] = *reinterpret_cast<const u32*>(pa + 8 * PK);
            af[mt][2] = *reinterpret_cast<const u32*>(pa + 8);
            af[mt][3] = *reinterpret_cast<const u32*>(pa + 8 * PK + 8);
        }
        #pragma unroll
        for (int nt = 0; nt < 8; nt++) {
            const u16* pb = smB + (wj + nt * 8 + gid) * PK + k0 + ctid * 2;
            bf[nt][0] = *reinterpret_cast<const u32*>(pb);
            bf[nt][1] = *reinterpret_cast<const u32*>(pb + 8);
        }
        #pragma unroll
        for (int mt = 0; mt < 2; mt++)
            #pragma unroll
            for (int nt = 0; nt < 8; nt++) {
                asm volatile(
                    "mma.sync.aligned.m16n8k16.row.col.f32.f16.f16.f32 "
                    "{%0,%1,%2,%3}, {%4,%5,%6,%7}, {%8,%9}, {%0,%1,%2,%3};"
                    : "+f"(acc[mt][nt][0]), "+f"(acc[mt][nt][1]),
                      "+f"(acc[mt][nt][2]), "+f"(acc[mt][nt][3])
                    : "r"(af[mt][0]), "r"(af[mt][1]), "r"(af[mt][2]), "r"(af[mt][3]),
                      "r"(bf[nt][0]), "r"(bf[nt][1]));
            }
    }
    __syncthreads();   // everyone done reading smA/smB

    // Epilogue: dist = sqi + sqj - 2*dot -> transformed fp16 pairs into dt.
    #pragma unroll
    for (int mt = 0; mt < 2; mt++) {
        const int r0 = wi + mt * 16 + gid, r1 = r0 + 8;
        float si0 = sqi[r0], si1 = sqi[r1];
        #pragma unroll
        for (int nt = 0; nt < 8; nt++) {
            const int c0 = wj + nt * 8 + ctid * 2;
            float sj0 = sqj[c0], sj1 = sqj[c0 + 1];
            float d00 = fmaf(-2.f, acc[mt][nt][0], si0 + sj0);
            float d01 = fmaf(-2.f, acc[mt][nt][1], si0 + sj1);
            float d10 = fmaf(-2.f, acc[mt][nt][2], si1 + sj0);
            float d11 = fmaf(-2.f, acc[mt][nt][3], si1 + sj1);
            u32 p0, p1;
            asm("cvt.rn.f16x2.f32 %0, %1, %2;" : "=r"(p0) : "f"(d01), "f"(d00));
            asm("cvt.rn.f16x2.f32 %0, %1, %2;" : "=r"(p1) : "f"(d11), "f"(d10));
            *reinterpret_cast<u32*>(dt + r0 * PDT + c0) = xform2(p0);
            *reinterpret_cast<u32*>(dt + r1 * PDT + c0) = xform2(p1);
        }
    }
    __syncthreads();

    // Coalesced writeout: 128 rows x 256B.
    for (int u = t; u < 128 * 16; u += 256) {
        int r = u >> 4, q = u & 15;
        uint4 v = *reinterpret_cast<const uint4*>(dt + r * PDT + q * 8);
        reinterpret_cast<uint4*>(g_dist + (size_t)(ib + r) * NN + jb)[q] = v;
    }
}

// ---------------------------------------------------------------------------
// Kernel 3: selection. Warp per row: stream dist row, per-lane sorted top-8
// (u32 keys: d16<<16 | j), exact fp32 rerank of own 8, warp-merge top-16.
// ---------------------------------------------------------------------------
__device__ __forceinline__ void ins8(u32* kd, u32 key) {
    if (key < kd[7]) {
        kd[7] = key;
        #pragma unroll
        for (int n = 7; n > 0; n--) {
            if (kd[n] < kd[n - 1]) { u32 tmp = kd[n]; kd[n] = kd[n - 1]; kd[n - 1] = tmp; }
            else break;
        }
    }
}

__global__ __launch_bounds__(256) void select_kernel(const float* __restrict__ x) {
    __shared__ float sxi[8][D];
    const int t = threadIdx.x;
    const int w = t >> 5, lane = t & 31;
    const int i = blockIdx.x * 8 + w;

    if (lane < 16)
        reinterpret_cast<uint4*>(sxi[w])[lane] =
            reinterpret_cast<const uint4*>(x + (size_t)i * D)[lane];
    __syncwarp();

    u32 kd[8];
    #pragma unroll
    for (int n = 0; n < 8; n++) kd[n] = 0xFFFFFFFFu;

    const uint4* rowp = reinterpret_cast<const uint4*>(g_dist + (size_t)i * NN);
    #pragma unroll 2
    for (int it = 0; it < 32; it++) {
        uint4 v = rowp[it * 32 + lane];
        const int jb = it * 256 + lane * 8;
        ins8(kd, (v.x << 16) | (u32)(jb + 0));
        ins8(kd, (v.x & 0xFFFF0000u) | (u32)(jb + 1));
        ins8(kd, (v.y << 16) | (u32)(jb + 2));
        ins8(kd, (v.y & 0xFFFF0000u) | (u32)(jb + 3));
        ins8(kd, (v.z << 16) | (u32)(jb + 4));
        ins8(kd, (v.z & 0xFFFF0000u) | (u32)(jb + 5));
        ins8(kd, (v.w << 16) | (u32)(jb + 6));
        ins8(kd, (v.w & 0xFFFF0000u) | (u32)(jb + 7));
    }

    // Exact fp32 rerank of this lane's 8 candidates.
    const float sqiv = g_sq[i];
    u64 ek[8];
    const float4* xi4 = reinterpret_cast<const float4*>(sxi[w]);
    #pragma unroll 1
    for (int c = 0; c < 8; c++) {
        const int j = (int)(kd[c] & 0xFFFFu);
        const float4* xj = reinterpret_cast<const float4*>(x + (size_t)j * D);
        float ax = 0.f, ay = 0.f, az = 0.f, aw = 0.f;
        #pragma unroll
        for (int q = 0; q < 16; q++) {
            float4 a = xi4[q], b = xj[q];
            ax = fmaf(a.x, b.x, ax); ay = fmaf(a.y, b.y, ay);
            az = fmaf(a.z, b.z, az); aw = fmaf(a.w, b.w, aw);
        }
        float dot = (ax + ay) + (az + aw);
        float dist = fmaf(-2.f, dot, sqiv + g_sq[j]);
        u32 u = __float_as_uint(dist);
        u = (u & 0x80000000u) ? ~u : (u | 0x80000000u);
        ek[c] = ((u64)u << 32) | (u32)j;
    }
    // Sort 8 ascending (unrolled insertion).
    #pragma unroll
    for (int a2 = 1; a2 < 8; a2++)
        #pragma unroll
        for (int b2 = a2; b2 > 0; b2--) {
            if (ek[b2] < ek[b2 - 1]) { u64 tmp = ek[b2]; ek[b2] = ek[b2 - 1]; ek[b2 - 1] = tmp; }
        }

    // 16 rounds of warp-min over heads; winner shifts its list.
    for (int r = 0; r < K; r++) {
        u64 h = ek[0];
        u64 m = h;
        #pragma unroll
        for (int off = 16; off > 0; off >>= 1) {
            u64 o = __shfl_down_sync(0xFFFFFFFFu, m, off);
            if (o < m) m = o;
        }
        m = __shfl_sync(0xFFFFFFFFu, m, 0);
        if (h == m) {
            g_nbr[(size_t)i * K + r] = (int)(m & 0xFFFFu);
            #pragma unroll
            for (int c = 0; c < 7; c++) ek[c] = ek[c + 1];
            ek[7] = 0xFFFFFFFFFFFFFFFFull;
        }
    }
}

// ---------------------------------------------------------------------------
// Kernel 4: aggregate r = mean_n relu(p_i + q_jn), out = r@W2 + b2.
// ---------------------------------------------------------------------------
__global__ __launch_bounds__(128) void agg_kernel(const float* __restrict__ W2,
                                                  const float* __restrict__ b2,
                                                  float* __restrict__ out) {
    __shared__ int snbr[K];
    __shared__ float sr[DO];
    const int i = blockIdx.x;
    const int t = threadIdx.x;

    if (t < K) snbr[t] = g_nbr[(size_t)i * K + t];
    __syncthreads();

    float p = g_p[(size_t)i * DO + t];
    float acc = 0.f;
    #pragma unroll
    for (int n = 0; n < K; n++) {
        int j = snbr[n];
        acc += fmaxf(p + g_q[(size_t)j * DO + t], 0.f);
    }
    sr[t] = acc * (1.f / K);
    __syncthreads();

    float o = b2[t];
    #pragma unroll 8
    for (int d = 0; d < DO; d++)
        o = fmaf(sr[d], W2[d * DO + t], o);
    out[(size_t)i * DO + t] = o;
}

// ---------------------------------------------------------------------------
extern "C" void kernel_launch(void* const* d_in, const int* in_sizes, int n_in,
                              void* d_out, int out_size) {
    const float* x  = (const float*)d_in[0];
    const float* W1 = (const float*)d_in[1];
    const float* b1 = (const float*)d_in[2];
    const float* W2 = (const float*)d_in[3];
    const float* b2 = (const float*)d_in[4];
    float* out = (float*)d_out;

    pq_kernel<<<NN / 8, 256>>>(x, W1, b1);
    dist_kernel<<<dim3(NN / 128, NN / 128), 256, DIST_SMEM>>>();
    select_kernel<<<NN / 8, 256>>>(x);
    agg_kernel<<<NN, 128>>>(W2, b2, out);
}

// round 9
// speedup vs baseline: 9.6802x; 9.6802x over previous
#include <cuda_runtime.h>
#include <cstdint>

#define NN 8192
#define D 64
#define DO 128
#define K 16
#define SEG 16
#define JSEG (NN/SEG)       // 512
#define TJ 64

typedef unsigned long long u64;

// Scratch (no allocs allowed in kernel_launch)
__device__ float g_sq[NN];
__device__ float g_p[NN * DO];
__device__ float g_q[NN * DO];
__device__ u64 g_ck[NN * SEG * K];

// Packed fp32x2 math (Blackwell FFMA2 path — only reachable via PTX)
__device__ __forceinline__ u64 ffma2(u64 a, u64 b, u64 c) {
    u64 d;
    asm("fma.rn.f32x2 %0, %1, %2, %3;" : "=l"(d) : "l"(a), "l"(b), "l"(c));
    return d;
}
__device__ __forceinline__ u64 fadd2(u64 a, u64 b) {
    u64 d;
    asm("add.rn.f32x2 %0, %1, %2;" : "=l"(d) : "l"(a), "l"(b));
    return d;
}

// ---------------------------------------------------------------------------
// Kernel 1: per-row squared norms + p = x@(W1a-W1b)+b1, q = x@W1b
// ---------------------------------------------------------------------------
__global__ __launch_bounds__(256) void pq_kernel(const float* __restrict__ x,
                                                 const float* __restrict__ W1,
                                                 const float* __restrict__ b1) {
    __shared__ float sx[8 * D];
    const int i0 = blockIdx.x * 8;
    const int t = threadIdx.x;

    for (int u = t; u < 8 * D; u += 256) sx[u] = x[i0 * D + u];
    __syncthreads();

    if (t < 8) {
        float s = 0.f;
        #pragma unroll
        for (int d = 0; d < D; d++) { float v = sx[t * D + d]; s = fmaf(v, v, s); }
        g_sq[i0 + t] = s;
    }

    float acc[8];
    #pragma unroll
    for (int m = 0; m < 8; m++) acc[m] = 0.f;

    if (t < DO) {
        const int c = t;
        for (int d = 0; d < D; d++) {
            float w = W1[d * DO + c] - W1[(D + d) * DO + c];
            #pragma unroll
            for (int m = 0; m < 8; m++) acc[m] = fmaf(sx[m * D + d], w, acc[m]);
        }
        float bb = b1[c];
        #pragma unroll
        for (int m = 0; m < 8; m++) g_p[(size_t)(i0 + m) * DO + c] = acc[m] + bb;
    } else {
        const int c = t - DO;
        for (int d = 0; d < D; d++) {
            float w = W1[(D + d) * DO + c];
            #pragma unroll
            for (int m = 0; m < 8; m++) acc[m] = fmaf(sx[m * D + d], w, acc[m]);
        }
        #pragma unroll
        for (int m = 0; m < 8; m++) g_q[(size_t)(i0 + m) * DO + c] = acc[m];
    }
}

// ---------------------------------------------------------------------------
// Kernel 2: kNN (R2 structure, 4x grid). grid = (N/128, SEG=16). Each thread
// owns query row i and scans j in its 512-wide segment, sorted top-16 in regs.
// ---------------------------------------------------------------------------
__global__ __launch_bounds__(128, 4) void knn_kernel(const float* __restrict__ x) {
    __shared__ ulonglong2 sj[TJ * 16];   // 64 rows x 256B verbatim
    __shared__ float ssq[TJ];
    const int tid = threadIdx.x;
    const int i = blockIdx.x * 128 + tid;
    const int s = blockIdx.y;

    // Query row packed as 16x ulonglong2 (32 f32x2 pairs) in registers.
    ulonglong2 xi[16];
    const ulonglong2* xr = reinterpret_cast<const ulonglong2*>(x) + (size_t)i * 16;
    #pragma unroll
    for (int c = 0; c < 16; c++) xi[c] = xr[c];
    const float sqi = g_sq[i];

    float kd[K];
    int   kj[K];
    #pragma unroll
    for (int n = 0; n < K; n++) { kd[n] = 3.4e38f; kj[n] = 0; }

    const int jbeg = s * JSEG, jend = jbeg + JSEG;
    for (int jb = jbeg; jb < jend; jb += TJ) {
        const ulonglong2* gs = reinterpret_cast<const ulonglong2*>(x) + (size_t)jb * 16;
        #pragma unroll
        for (int u = tid; u < TJ * 16; u += 128) sj[u] = gs[u];
        if (tid < TJ) ssq[tid] = g_sq[jb + tid];
        __syncthreads();

        #pragma unroll 2
        for (int jj = 0; jj < TJ; jj++) {
            u64 a0 = 0ull, a1 = 0ull, a2 = 0ull, a3 = 0ull;
            #pragma unroll
            for (int c = 0; c < 16; c += 2) {
                ulonglong2 v0 = sj[jj * 16 + c];
                ulonglong2 v1 = sj[jj * 16 + c + 1];
                a0 = ffma2(xi[c].x, v0.x, a0);
                a1 = ffma2(xi[c].y, v0.y, a1);
                a2 = ffma2(xi[c + 1].x, v1.x, a2);
                a3 = ffma2(xi[c + 1].y, v1.y, a3);
            }
            u64 st = fadd2(fadd2(a0, a1), fadd2(a2, a3));
            unsigned lo, hi;
            asm("mov.b64 {%0, %1}, %2;" : "=r"(lo), "=r"(hi) : "l"(st));
            float dot = __uint_as_float(lo) + __uint_as_float(hi);
            float dist = fmaf(-2.f, dot, sqi + ssq[jj]);
            if (dist < kd[K - 1]) {
                kd[K - 1] = dist; kj[K - 1] = jb + jj;
                #pragma unroll
                for (int n = K - 1; n > 0; n--) {
                    if (kd[n] < kd[n - 1]) {
                        float td = kd[n]; kd[n] = kd[n - 1]; kd[n - 1] = td;
                        int   tj = kj[n]; kj[n] = kj[n - 1]; kj[n - 1] = tj;
                    }
                }
            }
        }
        __syncthreads();
    }

    u64* dst = g_ck + ((size_t)i * SEG + s) * K;
    #pragma unroll
    for (int n = 0; n < K; n++) {
        unsigned u = __float_as_uint(kd[n]);
        u = (u & 0x80000000u) ? ~u : (u | 0x80000000u);  // total order for floats
        dst[n] = ((u64)u << 32) | (unsigned)kj[n];
    }
}

// ---------------------------------------------------------------------------
// Kernel 3: per row i: merge SEG x 16 = 256 candidates -> final 16 neighbors
// (rank select, keys unique), aggregate r = mean_n relu(p_i + q_jn),
// out = r@W2 + b2. Block = 256 threads = one output row.
// ---------------------------------------------------------------------------
__global__ __launch_bounds__(256) void agg_kernel(const float* __restrict__ W2,
                                                  const float* __restrict__ b2,
                                                  float* __restrict__ out) {
    __shared__ u64 skey[SEG * K];    // 256
    __shared__ int snbr[K];
    __shared__ float sr[DO];
    const int i = blockIdx.x;
    const int t = threadIdx.x;

    skey[t] = g_ck[(size_t)i * SEG * K + t];
    __syncthreads();
    {
        u64 mk = skey[t];
        int rank = 0;
        #pragma unroll 8
        for (int u = 0; u < SEG * K; u++) rank += (skey[u] < mk);
        if (rank < K) snbr[rank] = (int)(mk & 0xFFFFFFFFull);
    }
    __syncthreads();

    if (t < DO) {
        float p = g_p[(size_t)i * DO + t];
        float acc = 0.f;
        #pragma unroll
        for (int n = 0; n < K; n++) {
            int j = snbr[n];
            acc += fmaxf(p + g_q[(size_t)j * DO + t], 0.f);
        }
        sr[t] = acc * (1.f / K);
    }
    __syncthreads();

    if (t < DO) {
        float o = b2[t];
        #pragma unroll 8
        for (int d = 0; d < DO; d++)
            o = fmaf(sr[d], W2[d * DO + t], o);
        out[(size_t)i * DO + t] = o;
    }
}

// ---------------------------------------------------------------------------
extern "C" void kernel_launch(void* const* d_in, const int* in_sizes, int n_in,
                              void* d_out, int out_size) {
    const float* x  = (const float*)d_in[0];
    const float* W1 = (const float*)d_in[1];
    const float* b1 = (const float*)d_in[2];
    const float* W2 = (const float*)d_in[3];
    const float* b2 = (const float*)d_in[4];
    float* out = (float*)d_out;

    pq_kernel<<<NN / 8, 256>>>(x, W1, b1);
    knn_kernel<<<dim3(NN / 128, SEG), 128>>>(x);
    agg_kernel<<<NN, 256>>>(W2, b2, out);
}

// round 10
// speedup vs baseline: 11.1955x; 1.1565x over previous
#include <cuda_runtime.h>
#include <cstdint>

#define NN 8192
#define D 64
#define DO 128
#define K 16

#define SEGA 8
#define JSEGA 128
#define SEGB 14
#define JSEGB 512
#define JB0 1024
#define CAP 96
#define TJ 64

typedef unsigned long long u64;
typedef unsigned int u32;

// Scratch (module-scope device arrays; no runtime allocs)
__device__ float g_sq[NN];
__device__ float g_p[NN * DO];
__device__ float g_q[NN * DO];
__device__ u64 g_ck[NN * SEGA * K];
__device__ float g_thr[NN];
__device__ u64 g_cand[(size_t)NN * SEGB * CAP];
__device__ int g_cnt[NN * SEGB];
__device__ int g_nbr[NN * K];

// Packed fp32x2 math (FFMA2 path, PTX-only)
__device__ __forceinline__ u64 ffma2(u64 a, u64 b, u64 c) {
    u64 d;
    asm("fma.rn.f32x2 %0, %1, %2, %3;" : "=l"(d) : "l"(a), "l"(b), "l"(c));
    return d;
}
__device__ __forceinline__ u64 fadd2(u64 a, u64 b) {
    u64 d;
    asm("add.rn.f32x2 %0, %1, %2;" : "=l"(d) : "l"(a), "l"(b));
    return d;
}
__device__ __forceinline__ u32 fkey(float f) {
    u32 u = __float_as_uint(f);
    return (u & 0x80000000u) ? ~u : (u | 0x80000000u);
}
__device__ __forceinline__ float unfkey(u32 u) {
    return __uint_as_float((u & 0x80000000u) ? (u & 0x7FFFFFFFu) : ~u);
}

// ---------------------------------------------------------------------------
// Kernel 1: per-row squared norms + p = x@(W1a-W1b)+b1, q = x@W1b
// ---------------------------------------------------------------------------
__global__ __launch_bounds__(256) void pq_kernel(const float* __restrict__ x,
                                                 const float* __restrict__ W1,
                                                 const float* __restrict__ b1) {
    __shared__ float sx[8 * D];
    const int i0 = blockIdx.x * 8;
    const int t = threadIdx.x;

    for (int u = t; u < 8 * D; u += 256) sx[u] = x[i0 * D + u];
    __syncthreads();

    if (t < 8) {
        float s = 0.f;
        #pragma unroll
        for (int d = 0; d < D; d++) { float v = sx[t * D + d]; s = fmaf(v, v, s); }
        g_sq[i0 + t] = s;
    }

    float acc[8];
    #pragma unroll
    for (int m = 0; m < 8; m++) acc[m] = 0.f;

    if (t < DO) {
        const int c = t;
        for (int d = 0; d < D; d++) {
            float w = W1[d * DO + c] - W1[(D + d) * DO + c];
            #pragma unroll
            for (int m = 0; m < 8; m++) acc[m] = fmaf(sx[m * D + d], w, acc[m]);
        }
        float bb = b1[c];
        #pragma unroll
        for (int m = 0; m < 8; m++) g_p[(size_t)(i0 + m) * DO + c] = acc[m] + bb;
    } else {
        const int c = t - DO;
        for (int d = 0; d < D; d++) {
            float w = W1[(D + d) * DO + c];
            #pragma unroll
            for (int m = 0; m < 8; m++) acc[m] = fmaf(sx[m * D + d], w, acc[m]);
        }
        #pragma unroll
        for (int m = 0; m < 8; m++) g_q[(size_t)(i0 + m) * DO + c] = acc[m];
    }
}

// ---------------------------------------------------------------------------
// Kernel 2a: phase A — exact top-16 per (row, 128-j subsegment), j < 1024.
// grid = (64, 8). Same structure as R9 (validated).
// ---------------------------------------------------------------------------
__global__ __launch_bounds__(128, 4) void knnA_kernel(const float* __restrict__ x) {
    __shared__ ulonglong2 sj[TJ * 16];
    __shared__ float ssq[TJ];
    const int tid = threadIdx.x;
    const int i = blockIdx.x * 128 + tid;
    const int s = blockIdx.y;

    ulonglong2 xi[16];
    const ulonglong2* xr = reinterpret_cast<const ulonglong2*>(x) + (size_t)i * 16;
    #pragma unroll
    for (int c = 0; c < 16; c++) xi[c] = xr[c];
    const float sqi = g_sq[i];

    float kd[K];
    int   kj[K];
    #pragma unroll
    for (int n = 0; n < K; n++) { kd[n] = 3.4e38f; kj[n] = 0; }

    const int jbeg = s * JSEGA, jend = jbeg + JSEGA;
    for (int jb = jbeg; jb < jend; jb += TJ) {
        const ulonglong2* gs = reinterpret_cast<const ulonglong2*>(x) + (size_t)jb * 16;
        #pragma unroll
        for (int u = tid; u < TJ * 16; u += 128) sj[u] = gs[u];
        if (tid < TJ) ssq[tid] = g_sq[jb + tid];
        __syncthreads();

        #pragma unroll 2
        for (int jj = 0; jj < TJ; jj++) {
            u64 a0 = 0ull, a1 = 0ull, a2 = 0ull, a3 = 0ull;
            #pragma unroll
            for (int c = 0; c < 16; c += 2) {
                ulonglong2 v0 = sj[jj * 16 + c];
                ulonglong2 v1 = sj[jj * 16 + c + 1];
                a0 = ffma2(xi[c].x, v0.x, a0);
                a1 = ffma2(xi[c].y, v0.y, a1);
                a2 = ffma2(xi[c + 1].x, v1.x, a2);
                a3 = ffma2(xi[c + 1].y, v1.y, a3);
            }
            u64 st = fadd2(fadd2(a0, a1), fadd2(a2, a3));
            unsigned lo, hi;
            asm("mov.b64 {%0, %1}, %2;" : "=r"(lo), "=r"(hi) : "l"(st));
            float dot = __uint_as_float(lo) + __uint_as_float(hi);
            float dist = fmaf(-2.f, dot, sqi + ssq[jj]);
            if (dist < kd[K - 1]) {
                kd[K - 1] = dist; kj[K - 1] = jb + jj;
                #pragma unroll
                for (int n = K - 1; n > 0; n--) {
                    if (kd[n] < kd[n - 1]) {
                        float td = kd[n]; kd[n] = kd[n - 1]; kd[n - 1] = td;
                        int   tj = kj[n]; kj[n] = kj[n - 1]; kj[n - 1] = tj;
                    }
                }
            }
        }
        __syncthreads();
    }

    u64* dst = g_ck + ((size_t)i * SEGA + s) * K;
    #pragma unroll
    for (int n = 0; n < K; n++)
        dst[n] = ((u64)fkey(kd[n]) << 32) | (unsigned)kj[n];
}

// ---------------------------------------------------------------------------
// Kernel 2b: threshold — exact 16th-smallest key of each row's 128 A-keys.
// Thread per row.
// ---------------------------------------------------------------------------
__global__ __launch_bounds__(128) void thresh_kernel() {
    const int i = blockIdx.x * 128 + threadIdx.x;
    const u64* src = g_ck + (size_t)i * SEGA * K;

    u64 kd[K];
    #pragma unroll
    for (int n = 0; n < K; n++) kd[n] = 0xFFFFFFFFFFFFFFFFull;

    for (int u = 0; u < SEGA * K; u++) {
        u64 e = src[u];
        if (e < kd[K - 1]) {
            kd[K - 1] = e;
            #pragma unroll
            for (int n = K - 1; n > 0; n--) {
                if (kd[n] < kd[n - 1]) { u64 tm = kd[n]; kd[n] = kd[n - 1]; kd[n - 1] = tm; }
                else break;
            }
        }
    }
    g_thr[i] = unfkey((u32)(kd[K - 1] >> 32));
}

// ---------------------------------------------------------------------------
// Kernel 2c: phase B — fixed-threshold candidate scan, j in [1024, 8192).
// grid = (64, 14). No top-k in the hot loop: dist + STS + mask bit; rare
// ffs-drain appends keys to per-(row,seg) gmem slab.
// ---------------------------------------------------------------------------
__global__ __launch_bounds__(128, 4) void knnB_kernel(const float* __restrict__ x) {
    __shared__ ulonglong2 sj[TJ * 16];
    __shared__ float ssq[TJ];
    __shared__ float sd[8 * 132];     // [u][tid] chunk scratch
    const int tid = threadIdx.x;
    const int i = blockIdx.x * 128 + tid;
    const int s = blockIdx.y;

    ulonglong2 xi[16];
    const ulonglong2* xr = reinterpret_cast<const ulonglong2*>(x) + (size_t)i * 16;
    #pragma unroll
    for (int c = 0; c < 16; c++) xi[c] = xr[c];
    const float sqi = g_sq[i];
    const float thr = g_thr[i];

    u64* cp = g_cand + ((size_t)i * SEGB + s) * CAP;
    int cnt = 0;

    const int jbeg = JB0 + s * JSEGB, jend = jbeg + JSEGB;
    for (int jb = jbeg; jb < jend; jb += TJ) {
        const ulonglong2* gs = reinterpret_cast<const ulonglong2*>(x) + (size_t)jb * 16;
        #pragma unroll
        for (int u = tid; u < TJ * 16; u += 128) sj[u] = gs[u];
        if (tid < TJ) ssq[tid] = g_sq[jb + tid];
        __syncthreads();

        #pragma unroll 1
        for (int c8 = 0; c8 < TJ / 8; c8++) {
            u32 mask = 0;
            #pragma unroll
            for (int u = 0; u < 8; u++) {
                const int jj = c8 * 8 + u;
                u64 a0 = 0ull, a1 = 0ull, a2 = 0ull, a3 = 0ull;
                #pragma unroll
                for (int c = 0; c < 16; c += 2) {
                    ulonglong2 v0 = sj[jj * 16 + c];
                    ulonglong2 v1 = sj[jj * 16 + c + 1];
                    a0 = ffma2(xi[c].x, v0.x, a0);
                    a1 = ffma2(xi[c].y, v0.y, a1);
                    a2 = ffma2(xi[c + 1].x, v1.x, a2);
                    a3 = ffma2(xi[c + 1].y, v1.y, a3);
                }
                u64 st = fadd2(fadd2(a0, a1), fadd2(a2, a3));
                unsigned lo, hi;
                asm("mov.b64 {%0, %1}, %2;" : "=r"(lo), "=r"(hi) : "l"(st));
                float dot = __uint_as_float(lo) + __uint_as_float(hi);
                float dist = fmaf(-2.f, dot, sqi + ssq[jj]);
                sd[u * 132 + tid] = dist;
                mask |= (dist <= thr) ? (1u << u) : 0u;
            }
            // Drain (rare): per-lane set bits.
            while (mask) {
                int b = __ffs(mask) - 1;
                mask &= mask - 1;
                float dv = sd[b * 132 + tid];
                int jv = jb + c8 * 8 + b;
                u64 key = ((u64)fkey(dv) << 32) | (u32)jv;
                int slot = (cnt < CAP) ? cnt : (CAP - 1);
                cp[slot] = key;
                cnt++;
            }
        }
        __syncthreads();
    }

    g_cnt[i * SEGB + s] = (cnt < CAP) ? cnt : CAP;
}

// ---------------------------------------------------------------------------
// Kernel 3: merge — warp per row over 128 A-keys + appended B-keys;
// per-lane sorted top-16, then 16-round warp-min extraction (R8-validated).
// ---------------------------------------------------------------------------
__global__ __launch_bounds__(256) void merge_kernel() {
    const int t = threadIdx.x;
    const int w = t >> 5, lane = t & 31;
    const int i = blockIdx.x * 8 + w;

    u64 kd[K];
    #pragma unroll
    for (int n = 0; n < K; n++) kd[n] = 0xFFFFFFFFFFFFFFFFull;

    const u64* ak = g_ck + (size_t)i * SEGA * K;
    for (int u = lane; u < SEGA * K; u += 32) {
        u64 e = ak[u];
        if (e < kd[K - 1]) {
            kd[K - 1] = e;
            #pragma unroll
            for (int n = K - 1; n > 0; n--) {
                if (kd[n] < kd[n - 1]) { u64 tm = kd[n]; kd[n] = kd[n - 1]; kd[n - 1] = tm; }
                else break;
            }
        }
    }
    for (int s = 0; s < SEGB; s++) {
        const int c = g_cnt[i * SEGB + s];
        const u64* p = g_cand + ((size_t)i * SEGB + s) * CAP;
        for (int u = lane; u < c; u += 32) {
            u64 e = p[u];
            if (e < kd[K - 1]) {
                kd[K - 1] = e;
                #pragma unroll
                for (int n = K - 1; n > 0; n--) {
                    if (kd[n] < kd[n - 1]) { u64 tm = kd[n]; kd[n] = kd[n - 1]; kd[n - 1] = tm; }
                    else break;
                }
            }
        }
    }

    // 16 rounds: global min over sorted heads; winner shifts its list.
    for (int r = 0; r < K; r++) {
        u64 h = kd[0];
        u64 m = h;
        #pragma unroll
        for (int off = 16; off > 0; off >>= 1) {
            u64 o = __shfl_down_sync(0xFFFFFFFFu, m, off);
            if (o < m) m = o;
        }
        m = __shfl_sync(0xFFFFFFFFu, m, 0);
        if (h == m) {
            g_nbr[(size_t)i * K + r] = (int)(m & 0xFFFFFFFFull);
            #pragma unroll
            for (int c = 0; c < K - 1; c++) kd[c] = kd[c + 1];
            kd[K - 1] = 0xFFFFFFFFFFFFFFFFull;
        }
    }
}

// ---------------------------------------------------------------------------
// Kernel 4: aggregate r = mean_n relu(p_i + q_jn), out = r@W2 + b2.
// ---------------------------------------------------------------------------
__global__ __launch_bounds__(128) void agg_kernel(const float* __restrict__ W2,
                                                  const float* __restrict__ b2,
                                                  float* __restrict__ out) {
    __shared__ int snbr[K];
    __shared__ float sr[DO];
    const int i = blockIdx.x;
    const int t = threadIdx.x;

    if (t < K) snbr[t] = g_nbr[(size_t)i * K + t];
    __syncthreads();

    float p = g_p[(size_t)i * DO + t];
    float acc = 0.f;
    #pragma unroll
    for (int n = 0; n < K; n++) {
        int j = snbr[n];
        acc += fmaxf(p + g_q[(size_t)j * DO + t], 0.f);
    }
    sr[t] = acc * (1.f / K);
    __syncthreads();

    float o = b2[t];
    #pragma unroll 8
    for (int d = 0; d < DO; d++)
        o = fmaf(sr[d], W2[d * DO + t], o);
    out[(size_t)i * DO + t] = o;
}

// ---------------------------------------------------------------------------
extern "C" void kernel_launch(void* const* d_in, const int* in_sizes, int n_in,
                              void* d_out, int out_size) {
    const float* x  = (const float*)d_in[0];
    const float* W1 = (const float*)d_in[1];
    const float* b1 = (const float*)d_in[2];
    const float* W2 = (const float*)d_in[3];
    const float* b2 = (const float*)d_in[4];
    float* out = (float*)d_out;

    pq_kernel<<<NN / 8, 256>>>(x, W1, b1);
    knnA_kernel<<<dim3(NN / 128, SEGA), 128>>>(x);
    thresh_kernel<<<NN / 128, 128>>>();
    knnB_kernel<<<dim3(NN / 128, SEGB), 128>>>(x);
    merge_kernel<<<NN / 8, 256>>>();
    agg_kernel<<<NN, 128>>>(W2, b2, out);
}

// round 11
// speedup vs baseline: 12.0660x; 1.0778x over previous
#include <cuda_runtime.h>
#include <cstdint>

#define NN 8192
#define D 64
#define DO 128
#define K 16

#define SEGA 8
#define JSEGA 128
#define SEGB 14
#define JSEGB 512
#define JB0 1024
#define CAP 96
#define TJ 64

typedef unsigned long long u64;
typedef unsigned int u32;

// Scratch (module-scope device arrays; no runtime allocs)
__device__ float g_sq[NN];
__device__ float g_p[NN * DO];
__device__ float g_q[NN * DO];
__device__ u64 g_ck[NN * SEGA * K];
__device__ float g_thr[NN];
__device__ u64 g_cand[(size_t)NN * SEGB * CAP];
__device__ int g_cnt[NN * SEGB];
__device__ int g_nbr[NN * K];

// Packed fp32x2 math (FFMA2 path, PTX-only)
__device__ __forceinline__ u64 ffma2(u64 a, u64 b, u64 c) {
    u64 d;
    asm("fma.rn.f32x2 %0, %1, %2, %3;" : "=l"(d) : "l"(a), "l"(b), "l"(c));
    return d;
}
__device__ __forceinline__ u64 fadd2(u64 a, u64 b) {
    u64 d;
    asm("add.rn.f32x2 %0, %1, %2;" : "=l"(d) : "l"(a), "l"(b));
    return d;
}
__device__ __forceinline__ u32 fkey(float f) {
    u32 u = __float_as_uint(f);
    return (u & 0x80000000u) ? ~u : (u | 0x80000000u);
}
__device__ __forceinline__ float unfkey(u32 u) {
    return __uint_as_float((u & 0x80000000u) ? (u & 0x7FFFFFFFu) : ~u);
}

// ---------------------------------------------------------------------------
// Kernel 1: per-row squared norms + p = x@(W1a-W1b)+b1, q = x@W1b
// ---------------------------------------------------------------------------
__global__ __launch_bounds__(256) void pq_kernel(const float* __restrict__ x,
                                                 const float* __restrict__ W1,
                                                 const float* __restrict__ b1) {
    __shared__ float sx[8 * D];
    const int i0 = blockIdx.x * 8;
    const int t = threadIdx.x;

    for (int u = t; u < 8 * D; u += 256) sx[u] = x[i0 * D + u];
    __syncthreads();

    if (t < 8) {
        float s = 0.f;
        #pragma unroll
        for (int d = 0; d < D; d++) { float v = sx[t * D + d]; s = fmaf(v, v, s); }
        g_sq[i0 + t] = s;
    }

    float acc[8];
    #pragma unroll
    for (int m = 0; m < 8; m++) acc[m] = 0.f;

    if (t < DO) {
        const int c = t;
        for (int d = 0; d < D; d++) {
            float w = W1[d * DO + c] - W1[(D + d) * DO + c];
            #pragma unroll
            for (int m = 0; m < 8; m++) acc[m] = fmaf(sx[m * D + d], w, acc[m]);
        }
        float bb = b1[c];
        #pragma unroll
        for (int m = 0; m < 8; m++) g_p[(size_t)(i0 + m) * DO + c] = acc[m] + bb;
    } else {
        const int c = t - DO;
        for (int d = 0; d < D; d++) {
            float w = W1[(D + d) * DO + c];
            #pragma unroll
            for (int m = 0; m < 8; m++) acc[m] = fmaf(sx[m * D + d], w, acc[m]);
        }
        #pragma unroll
        for (int m = 0; m < 8; m++) g_q[(size_t)(i0 + m) * DO + c] = acc[m];
    }
}

// ---------------------------------------------------------------------------
// Kernel 2a: phase A — exact top-16 per (row, 128-j subsegment), j < 1024.
// grid = (64, 8). Validated in R10.
// ---------------------------------------------------------------------------
__global__ __launch_bounds__(128, 4) void knnA_kernel(const float* __restrict__ x) {
    __shared__ ulonglong2 sj[TJ * 16];
    __shared__ float ssq[TJ];
    const int tid = threadIdx.x;
    const int i = blockIdx.x * 128 + tid;
    const int s = blockIdx.y;

    ulonglong2 xi[16];
    const ulonglong2* xr = reinterpret_cast<const ulonglong2*>(x) + (size_t)i * 16;
    #pragma unroll
    for (int c = 0; c < 16; c++) xi[c] = xr[c];
    const float sqi = g_sq[i];

    float kd[K];
    int   kj[K];
    #pragma unroll
    for (int n = 0; n < K; n++) { kd[n] = 3.4e38f; kj[n] = 0; }

    const int jbeg = s * JSEGA, jend = jbeg + JSEGA;
    for (int jb = jbeg; jb < jend; jb += TJ) {
        const ulonglong2* gs = reinterpret_cast<const ulonglong2*>(x) + (size_t)jb * 16;
        #pragma unroll
        for (int u = tid; u < TJ * 16; u += 128) sj[u] = gs[u];
        if (tid < TJ) ssq[tid] = g_sq[jb + tid];
        __syncthreads();

        #pragma unroll 2
        for (int jj = 0; jj < TJ; jj++) {
            u64 a0 = 0ull, a1 = 0ull, a2 = 0ull, a3 = 0ull;
            #pragma unroll
            for (int c = 0; c < 16; c += 2) {
                ulonglong2 v0 = sj[jj * 16 + c];
                ulonglong2 v1 = sj[jj * 16 + c + 1];
                a0 = ffma2(xi[c].x, v0.x, a0);
                a1 = ffma2(xi[c].y, v0.y, a1);
                a2 = ffma2(xi[c + 1].x, v1.x, a2);
                a3 = ffma2(xi[c + 1].y, v1.y, a3);
            }
            u64 st = fadd2(fadd2(a0, a1), fadd2(a2, a3));
            unsigned lo, hi;
            asm("mov.b64 {%0, %1}, %2;" : "=r"(lo), "=r"(hi) : "l"(st));
            float dot = __uint_as_float(lo) + __uint_as_float(hi);
            float dist = fmaf(-2.f, dot, sqi + ssq[jj]);
            if (dist < kd[K - 1]) {
                kd[K - 1] = dist; kj[K - 1] = jb + jj;
                #pragma unroll
                for (int n = K - 1; n > 0; n--) {
                    if (kd[n] < kd[n - 1]) {
                        float td = kd[n]; kd[n] = kd[n - 1]; kd[n - 1] = td;
                        int   tj = kj[n]; kj[n] = kj[n - 1]; kj[n - 1] = tj;
                    }
                }
            }
        }
        __syncthreads();
    }

    u64* dst = g_ck + ((size_t)i * SEGA + s) * K;
    #pragma unroll
    for (int n = 0; n < K; n++)
        dst[n] = ((u64)fkey(kd[n]) << 32) | (unsigned)kj[n];
}

// ---------------------------------------------------------------------------
// Kernel 2b: threshold — exact 16th-smallest key of each row's 128 A-keys.
// ---------------------------------------------------------------------------
__global__ __launch_bounds__(128) void thresh_kernel() {
    const int i = blockIdx.x * 128 + threadIdx.x;
    const u64* src = g_ck + (size_t)i * SEGA * K;

    u64 kd[K];
    #pragma unroll
    for (int n = 0; n < K; n++) kd[n] = 0xFFFFFFFFFFFFFFFFull;

    for (int u = 0; u < SEGA * K; u++) {
        u64 e = src[u];
        if (e < kd[K - 1]) {
            kd[K - 1] = e;
            #pragma unroll
            for (int n = K - 1; n > 0; n--) {
                if (kd[n] < kd[n - 1]) { u64 tm = kd[n]; kd[n] = kd[n - 1]; kd[n - 1] = tm; }
                else break;
            }
        }
    }
    g_thr[i] = unfkey((u32)(kd[K - 1] >> 32));
}

// ---------------------------------------------------------------------------
// Kernel 2c: phase B — fixed-threshold scan, j in [1024, 8192), 2 rows/thread.
// grid = (32, 14), block 128. Same 16 LDS.128 per j now feed 64 FFMA2.
// ---------------------------------------------------------------------------
__global__ __launch_bounds__(128, 2) void knnB_kernel(const float* __restrict__ x) {
    __shared__ ulonglong2 sj[TJ * 16];
    __shared__ float ssq[TJ];
    __shared__ float sd[16 * 132];    // rows 0-7: row A dists, 8-15: row B
    const int tid = threadIdx.x;
    const int iA = blockIdx.x * 256 + tid;
    const int iB = iA + 128;
    const int s = blockIdx.y;

    ulonglong2 xa[16], xb[16];
    const ulonglong2* ra = reinterpret_cast<const ulonglong2*>(x) + (size_t)iA * 16;
    const ulonglong2* rb = reinterpret_cast<const ulonglong2*>(x) + (size_t)iB * 16;
    #pragma unroll
    for (int c = 0; c < 16; c++) { xa[c] = ra[c]; xb[c] = rb[c]; }
    const float sqa = g_sq[iA], sqb = g_sq[iB];
    const float tha = g_thr[iA], thb = g_thr[iB];

    u64* cpa = g_cand + ((size_t)iA * SEGB + s) * CAP;
    u64* cpb = g_cand + ((size_t)iB * SEGB + s) * CAP;
    int ca = 0, cb = 0;

    const int jbeg = JB0 + s * JSEGB, jend = jbeg + JSEGB;
    for (int jb = jbeg; jb < jend; jb += TJ) {
        const ulonglong2* gs = reinterpret_cast<const ulonglong2*>(x) + (size_t)jb * 16;
        #pragma unroll
        for (int u = tid; u < TJ * 16; u += 128) sj[u] = gs[u];
        if (tid < TJ) ssq[tid] = g_sq[jb + tid];
        __syncthreads();

        #pragma unroll 1
        for (int c8 = 0; c8 < TJ / 8; c8++) {
            u32 ma = 0, mb = 0;
            #pragma unroll 2
            for (int u = 0; u < 8; u++) {
                const int jj = c8 * 8 + u;
                u64 a0 = 0ull, a1 = 0ull, a2 = 0ull, a3 = 0ull;
                u64 b0 = 0ull, b1 = 0ull, b2 = 0ull, b3 = 0ull;
                #pragma unroll
                for (int c = 0; c < 16; c += 2) {
                    ulonglong2 v0 = sj[jj * 16 + c];
                    ulonglong2 v1 = sj[jj * 16 + c + 1];
                    a0 = ffma2(xa[c].x, v0.x, a0);
                    a1 = ffma2(xa[c].y, v0.y, a1);
                    a2 = ffma2(xa[c + 1].x, v1.x, a2);
                    a3 = ffma2(xa[c + 1].y, v1.y, a3);
                    b0 = ffma2(xb[c].x, v0.x, b0);
                    b1 = ffma2(xb[c].y, v0.y, b1);
                    b2 = ffma2(xb[c + 1].x, v1.x, b2);
                    b3 = ffma2(xb[c + 1].y, v1.y, b3);
                }
                const float sjv = ssq[jj];
                u64 sta = fadd2(fadd2(a0, a1), fadd2(a2, a3));
                u64 stb = fadd2(fadd2(b0, b1), fadd2(b2, b3));
                unsigned lo, hi;
                asm("mov.b64 {%0, %1}, %2;" : "=r"(lo), "=r"(hi) : "l"(sta));
                float dA = fmaf(-2.f, __uint_as_float(lo) + __uint_as_float(hi),
                                sqa + sjv);
                asm("mov.b64 {%0, %1}, %2;" : "=r"(lo), "=r"(hi) : "l"(stb));
                float dB = fmaf(-2.f, __uint_as_float(lo) + __uint_as_float(hi),
                                sqb + sjv);
                sd[u * 132 + tid] = dA;
                sd[(8 + u) * 132 + tid] = dB;
                ma |= (dA <= tha) ? (1u << u) : 0u;
                mb |= (dB <= thb) ? (1u << u) : 0u;
            }
            // Drain (rare).
            while (ma) {
                int b = __ffs(ma) - 1;
                ma &= ma - 1;
                float dv = sd[b * 132 + tid];
                int jv = jb + c8 * 8 + b;
                int slot = (ca < CAP) ? ca : (CAP - 1);
                cpa[slot] = ((u64)fkey(dv) << 32) | (u32)jv;
                ca++;
            }
            while (mb) {
                int b = __ffs(mb) - 1;
                mb &= mb - 1;
                float dv = sd[(8 + b) * 132 + tid];
                int jv = jb + c8 * 8 + b;
                int slot = (cb < CAP) ? cb : (CAP - 1);
                cpb[slot] = ((u64)fkey(dv) << 32) | (u32)jv;
                cb++;
            }
        }
        __syncthreads();
    }

    g_cnt[iA * SEGB + s] = (ca < CAP) ? ca : CAP;
    g_cnt[iB * SEGB + s] = (cb < CAP) ? cb : CAP;
}

// ---------------------------------------------------------------------------
// Kernel 3: merge — warp per row over 128 A-keys + appended B-keys;
// per-lane sorted top-16, then 16-round warp-min extraction.
// ---------------------------------------------------------------------------
__global__ __launch_bounds__(256) void merge_kernel() {
    const int t = threadIdx.x;
    const int w = t >> 5, lane = t & 31;
    const int i = blockIdx.x * 8 + w;

    u64 kd[K];
    #pragma unroll
    for (int n = 0; n < K; n++) kd[n] = 0xFFFFFFFFFFFFFFFFull;

    const u64* ak = g_ck + (size_t)i * SEGA * K;
    for (int u = lane; u < SEGA * K; u += 32) {
        u64 e = ak[u];
        if (e < kd[K - 1]) {
            kd[K - 1] = e;
            #pragma unroll
            for (int n = K - 1; n > 0; n--) {
                if (kd[n] < kd[n - 1]) { u64 tm = kd[n]; kd[n] = kd[n - 1]; kd[n - 1] = tm; }
                else break;
            }
        }
    }
    for (int s = 0; s < SEGB; s++) {
        const int c = g_cnt[i * SEGB + s];
        const u64* p = g_cand + ((size_t)i * SEGB + s) * CAP;
        for (int u = lane; u < c; u += 32) {
            u64 e = p[u];
            if (e < kd[K - 1]) {
                kd[K - 1] = e;
                #pragma unroll
                for (int n = K - 1; n > 0; n--) {
                    if (kd[n] < kd[n - 1]) { u64 tm = kd[n]; kd[n] = kd[n - 1]; kd[n - 1] = tm; }
                    else break;
                }
            }
        }
    }

    for (int r = 0; r < K; r++) {
        u64 h = kd[0];
        u64 m = h;
        #pragma unroll
        for (int off = 16; off > 0; off >>= 1) {
            u64 o = __shfl_down_sync(0xFFFFFFFFu, m, off);
            if (o < m) m = o;
        }
        m = __shfl_sync(0xFFFFFFFFu, m, 0);
        if (h == m) {
            g_nbr[(size_t)i * K + r] = (int)(m & 0xFFFFFFFFull);
            #pragma unroll
            for (int c = 0; c < K - 1; c++) kd[c] = kd[c + 1];
            kd[K - 1] = 0xFFFFFFFFFFFFFFFFull;
        }
    }
}

// ---------------------------------------------------------------------------
// Kernel 4: aggregate r = mean_n relu(p_i + q_jn), out = r@W2 + b2.
// ---------------------------------------------------------------------------
__global__ __launch_bounds__(128) void agg_kernel(const float* __restrict__ W2,
                                                  const float* __restrict__ b2,
                                                  float* __restrict__ out) {
    __shared__ int snbr[K];
    __shared__ float sr[DO];
    const int i = blockIdx.x;
    const int t = threadIdx.x;

    if (t < K) snbr[t] = g_nbr[(size_t)i * K + t];
    __syncthreads();

    float p = g_p[(size_t)i * DO + t];
    float acc = 0.f;
    #pragma unroll
    for (int n = 0; n < K; n++) {
        int j = snbr[n];
        acc += fmaxf(p + g_q[(size_t)j * DO + t], 0.f);
    }
    sr[t] = acc * (1.f / K);
    __syncthreads();

    float o = b2[t];
    #pragma unroll 8
    for (int d = 0; d < DO; d++)
        o = fmaf(sr[d], W2[d * DO + t], o);
    out[(size_t)i * DO + t] = o;
}

// ---------------------------------------------------------------------------
extern "C" void kernel_launch(void* const* d_in, const int* in_sizes, int n_in,
                              void* d_out, int out_size) {
    const float* x  = (const float*)d_in[0];
    const float* W1 = (const float*)d_in[1];
    const float* b1 = (const float*)d_in[2];
    const float* W2 = (const float*)d_in[3];
    const float* b2 = (const float*)d_in[4];
    float* out = (float*)d_out;

    pq_kernel<<<NN / 8, 256>>>(x, W1, b1);
    knnA_kernel<<<dim3(NN / 128, SEGA), 128>>>(x);
    thresh_kernel<<<NN / 128, 128>>>();
    knnB_kernel<<<dim3(NN / 256, SEGB), 128>>>(x);
    merge_kernel<<<NN / 8, 256>>>();
    agg_kernel<<<NN, 128>>>(W2, b2, out);
}